// round 4
// baseline (speedup 1.0000x reference)
#include <cuda_runtime.h>
#include <cuda_bf16.h>
#include <math.h>
#include <math_constants.h>

#define HB 512
#define WB 512
#define NB (HB*WB)          // 262144 BEV cells
#define NC 64               // channels
#define NBATCH 2
#define HR 64
#define WR 2048
#define NG 8                // row groups (8 rows each)
#define CAP2 512            // bucket capacity per (col,group)

// device scratch
__device__ float          g_rho[NB];
__device__ unsigned char  g_rowlow[NB];
__device__ unsigned short g_colb[NB];
__device__ int            g_cnt2[NBATCH * WR * NG];
__device__ unsigned int   g_item[(size_t)NBATCH * WR * NG * CAP2]; // (cell<<6)|(lo<<3)|hi
__device__ float          g_featT[(size_t)NBATCH * NB * NC];        // [B][N][C]

__device__ __forceinline__ float th_maxf()   { return (float)(3.0 * (CUDART_PI / 180.0)); }
__device__ __forceinline__ float th_rangef() {
    double tmax = 3.0 * (CUDART_PI / 180.0);
    double tmin = -25.0 * (CUDART_PI / 180.0);
    return (float)(tmax - tmin);
}
__device__ __forceinline__ float phi_minf()   { return (float)(-CUDART_PI); }
__device__ __forceinline__ float phi_rangef() { return (float)(2.0 * CUDART_PI); }

__device__ __forceinline__ int row_from_theta(float theta) {
    float v = __fmul_rn(__fdiv_rn(__fsub_rn(th_maxf(), theta), th_rangef()), 63.0f);
    v = rintf(v);
    v = fminf(fmaxf(v, 0.0f), 63.0f);
    return (int)v;
}

// ---------------- kernels ----------------
__global__ void k_zero() {
    int t = blockIdx.x * blockDim.x + threadIdx.x;
    if (t < NBATCH * WR * NG) g_cnt2[t] = 0;
}

__global__ void k_geom() {
    int n = blockIdx.x * blockDim.x + threadIdx.x;
    if (n >= NB) return;
    int i = n >> 9;
    int j = n & 511;
    float y = (float)(((double)i * (-100.0)) / 511.0 + 50.0);
    float x = (float)(((double)j * (100.0)) / 511.0 + (-50.0));
    float rho = __fsqrt_rn(__fadd_rn(__fmul_rn(x, x), __fmul_rn(y, y)));
    float phi = atan2f(y, x);
    float theta_low = atan2f(-1.73f, rho);

    int row_low = row_from_theta(theta_low);

    float cv = __fmul_rn(__fdiv_rn(__fsub_rn(phi, phi_minf()), phi_rangef()), 2047.0f);
    cv = rintf(cv);
    cv = fminf(fmaxf(cv, 0.0f), 2047.0f);
    int col = (int)cv;

    g_rho[n]    = rho;
    g_rowlow[n] = (unsigned char)row_low;
    g_colb[n]   = (unsigned short)col;
}

// per (b,cell): compute [rs,re], scatter into intersecting (col,row-group) buckets
__global__ void k_rowhi(const int* __restrict__ zbin) {
    int idx = blockIdx.x * blockDim.x + threadIdx.x;
    if (idx >= NBATCH * NB) return;
    int n = idx & (NB - 1);
    int b = idx >> 18;
    int zb = zbin[idx];
    float zh = __fadd_rn(__fmul_rn((float)zb, (float)(6.0 / 30.0)),
                         (float)(-4.0 + (6.0 / 30.0) / 2.0));
    float theta_hi = atan2f(zh, g_rho[n]);
    int row_hi  = row_from_theta(theta_hi);
    int row_low = (int)g_rowlow[n];
    int rs = min(row_low, row_hi);
    int re = max(row_low, row_hi);
    int col  = (int)g_colb[n];
    int base = (b * WR + col) * NG;
    int g0 = rs >> 3, g1 = re >> 3;
    for (int g = g0; g <= g1; ++g) {
        int lo = max(rs - g * 8, 0);
        int hi = min(re - g * 8, 7);
        int pos = atomicAdd(&g_cnt2[base + g], 1);
        if (pos < CAP2)
            g_item[(size_t)(base + g) * CAP2 + pos] =
                ((unsigned)n << 6) | ((unsigned)lo << 3) | (unsigned)hi;
    }
}

// [B,C,N] -> [B,N,C]; 64x32 tile per CTA (2 float4 loads in flight)
__global__ void k_transpose(const float* __restrict__ src) {
    __shared__ float tA[32][33];
    __shared__ float tB[32][33];
    int b  = blockIdx.z;
    int n0 = blockIdx.x * 64;
    int c0 = blockIdx.y * 32;
    int tx = threadIdx.x;   // 0..7
    int ty = threadIdx.y;   // 0..31
    const float* row = &src[((size_t)(b * NC + c0 + ty)) * NB + n0 + tx * 4];
    float4 fa = *(const float4*)row;
    float4 fb = *(const float4*)(row + 32);
    tA[tx * 4 + 0][ty] = fa.x; tA[tx * 4 + 1][ty] = fa.y;
    tA[tx * 4 + 2][ty] = fa.z; tA[tx * 4 + 3][ty] = fa.w;
    tB[tx * 4 + 0][ty] = fb.x; tB[tx * 4 + 1][ty] = fb.y;
    tB[tx * 4 + 2][ty] = fb.z; tB[tx * 4 + 3][ty] = fb.w;
    __syncthreads();
    float4 wa, wb;
    wa.x = tA[ty][tx * 4 + 0]; wa.y = tA[ty][tx * 4 + 1];
    wa.z = tA[ty][tx * 4 + 2]; wa.w = tA[ty][tx * 4 + 3];
    wb.x = tB[ty][tx * 4 + 0]; wb.y = tB[ty][tx * 4 + 1];
    wb.z = tB[ty][tx * 4 + 2]; wb.w = tB[ty][tx * 4 + 3];
    *(float4*)&g_featT[((size_t)b * NB + (n0 + ty)) * NC + c0 + tx * 4]      = wa;
    *(float4*)&g_featT[((size_t)b * NB + (n0 + 32 + ty)) * NC + c0 + tx * 4] = wb;
}

// CTA = (col, b). 8 warps = 8 row groups; lane owns 2 channels; acc in regs.
// Writes out[b][c][r][col] directly (scattered STG, merged in L2) with -inf->0.
__global__ void __launch_bounds__(256) k_project(float* __restrict__ out) {
    int col = blockIdx.x;
    int b   = blockIdx.y;
    int t    = threadIdx.x;
    int g    = t >> 5;
    int lane = t & 31;

    const float NF = -CUDART_INF_F;
    float2 a0 = make_float2(NF, NF);
    float2 a1 = a0, a2 = a0, a3 = a0, a4 = a0, a5 = a0, a6 = a0, a7 = a0;

    int base = (b * WR + col) * NG + g;
    int cnt  = min(g_cnt2[base], CAP2);
    const unsigned* items  = g_item + (size_t)base * CAP2;
    const float2*   featT2 = (const float2*)g_featT + (size_t)b * NB * 32;

    unsigned it_n = 0;
    float2   v_n  = make_float2(0.f, 0.f);
    if (cnt > 0) {
        it_n = items[0];
        v_n  = __ldg(&featT2[((size_t)(it_n >> 6) << 5) + lane]);
    }
    for (int i = 0; i < cnt; ++i) {
        unsigned it = it_n;
        float2   v  = v_n;
        if (i + 1 < cnt) {
            it_n = items[i + 1];
            v_n  = __ldg(&featT2[((size_t)(it_n >> 6) << 5) + lane]);
        }
        int lo = (it >> 3) & 7;
        int hi = it & 7;
        unsigned m = (0xFFu >> (7 - hi)) & (0xFFu << lo);
        if (m & 0x01u) { a0.x = fmaxf(a0.x, v.x); a0.y = fmaxf(a0.y, v.y); }
        if (m & 0x02u) { a1.x = fmaxf(a1.x, v.x); a1.y = fmaxf(a1.y, v.y); }
        if (m & 0x04u) { a2.x = fmaxf(a2.x, v.x); a2.y = fmaxf(a2.y, v.y); }
        if (m & 0x08u) { a3.x = fmaxf(a3.x, v.x); a3.y = fmaxf(a3.y, v.y); }
        if (m & 0x10u) { a4.x = fmaxf(a4.x, v.x); a4.y = fmaxf(a4.y, v.y); }
        if (m & 0x20u) { a5.x = fmaxf(a5.x, v.x); a5.y = fmaxf(a5.y, v.y); }
        if (m & 0x40u) { a6.x = fmaxf(a6.x, v.x); a6.y = fmaxf(a6.y, v.y); }
        if (m & 0x80u) { a7.x = fmaxf(a7.x, v.x); a7.y = fmaxf(a7.y, v.y); }
    }

    // epilogue: out[((b*NC + c)*HR + r)*WR + col], -inf -> 0
    int c = lane * 2;
    float* o0 = out + ((size_t)(b * NC + c) * HR + g * 8) * WR + col;       // channel c
    float* o1 = o0 + (size_t)HR * WR;                                       // channel c+1
    float rx, ry;
    rx = a0.x; ry = a0.y; o0[0 * WR] = (rx == NF) ? 0.f : rx; o1[0 * WR] = (ry == NF) ? 0.f : ry;
    rx = a1.x; ry = a1.y; o0[1 * WR] = (rx == NF) ? 0.f : rx; o1[1 * WR] = (ry == NF) ? 0.f : ry;
    rx = a2.x; ry = a2.y; o0[2 * WR] = (rx == NF) ? 0.f : rx; o1[2 * WR] = (ry == NF) ? 0.f : ry;
    rx = a3.x; ry = a3.y; o0[3 * WR] = (rx == NF) ? 0.f : rx; o1[3 * WR] = (ry == NF) ? 0.f : ry;
    rx = a4.x; ry = a4.y; o0[4 * WR] = (rx == NF) ? 0.f : rx; o1[4 * WR] = (ry == NF) ? 0.f : ry;
    rx = a5.x; ry = a5.y; o0[5 * WR] = (rx == NF) ? 0.f : rx; o1[5 * WR] = (ry == NF) ? 0.f : ry;
    rx = a6.x; ry = a6.y; o0[6 * WR] = (rx == NF) ? 0.f : rx; o1[6 * WR] = (ry == NF) ? 0.f : ry;
    rx = a7.x; ry = a7.y; o0[7 * WR] = (rx == NF) ? 0.f : rx; o1[7 * WR] = (ry == NF) ? 0.f : ry;
}

extern "C" void kernel_launch(void* const* d_in, const int* in_sizes, int n_in,
                              void* d_out, int out_size) {
    const float* feat = (const float*)d_in[0];   // [2,64,512,512] f32
    const int*   zbin = (const int*)d_in[1];     // [2,1,512,512] i32
    float*       out  = (float*)d_out;           // [2,64,64,2048] f32

    k_zero<<<(NBATCH * WR * NG + 255) / 256, 256>>>();
    k_geom<<<NB / 256, 256>>>();
    k_rowhi<<<(NBATCH * NB) / 256, 256>>>(zbin);
    k_transpose<<<dim3(NB / 64, NC / 32, NBATCH), dim3(8, 32)>>>(feat);
    k_project<<<dim3(WR, NBATCH), 256>>>(out);
}